// round 16
// baseline (speedup 1.0000x reference)
#include <cuda_runtime.h>
#include <cstdint>
#include <math_constants.h>

#define LOG2E 1.4426950408889634f

typedef unsigned long long u64;

// Scratch: 16 m-chunks x (8*4096) n's: lag-shifted partial sums + shift.
__device__ float g_partE[16 * 32768];
__device__ float g_partT[16 * 32768];
__device__ float g_partM[16 * 32768];

__device__ __forceinline__ u64 f2fma(u64 a, u64 b, u64 c) {
    u64 r; asm("fma.rn.f32x2 %0,%1,%2,%3;" : "=l"(r) : "l"(a), "l"(b), "l"(c)); return r;
}
__device__ __forceinline__ u64 f2add(u64 a, u64 b) {
    u64 r; asm("add.rn.f32x2 %0,%1,%2;" : "=l"(r) : "l"(a), "l"(b)); return r;
}
__device__ __forceinline__ u64 f2mul(u64 a, u64 b) {
    u64 r; asm("mul.rn.f32x2 %0,%1,%2;" : "=l"(r) : "l"(a), "l"(b)); return r;
}
__device__ __forceinline__ u64 pk(float lo, float hi) {
    u64 r; asm("mov.b64 %0,{%1,%2};" : "=l"(r) : "f"(lo), "f"(hi)); return r;
}
__device__ __forceinline__ void up(u64 v, float& lo, float& hi) {
    asm("mov.b64 {%0,%1},%2;" : "=f"(lo), "=f"(hi) : "l"(v));
}
__device__ __forceinline__ float ex2f(float x) {
    float r; asm("ex2.approx.f32 %0,%1;" : "=f"(r) : "f"(x)); return r;
}

// B=8, N=4096, M=4096, D=3 hardcoded.
// Grid: 1024 blocks = 8 batches x 8 n-chunks x 16 m-chunks.
// Block: 256 threads; each thread owns 2 n's; block owns 256 m's. 8-m tiles.
// Lagged-shift softmax: accumulate 2^(g-Sh); Sh raised only on a rare
// warp-uniform vote. No true-max tracking — the combine is exact for any
// per-chunk reference, and Sh is always a real logit (tile 0 always votes),
// preserving E >= 1 globally. LDS software-pipelined one tile ahead.
__global__ void __launch_bounds__(256, 2) fape_fused_kernel(
    const float* __restrict__ Xp,   // (8,4096,3)
    const float* __restrict__ Xt,   // (8,4096,3)
    const float* __restrict__ Rp,   // (8,3,3)
    const float* __restrict__ tp,   // (8,3)
    const float* __restrict__ Rt,   // (8,3,3)
    const float* __restrict__ tt,   // (8,3)
    const float* __restrict__ temp, // (1,)
    float* __restrict__ out)
{
    // 128 m-pair groups x 4 packed u64 + 16 pad (safe last prefetch).
    __shared__ __align__(16) u64 sm[128 * 4 + 16];

    const int mchunk = blockIdx.x & 15;
    const int nchunk = (blockIdx.x >> 4) & 7;
    const int b      = blockIdx.x >> 7;
    const int tid    = threadIdx.x;

    if (blockIdx.x == 0 && tid == 0) *out = 0.0f;   // reduce accumulates

    const float T = *temp;
    const float s = -LOG2E / T;   // logit scale in log2 domain (s < 0)

    // ---- Fill smem: v = (s*-2*Xt', s*|Xt'|^2) for this block's 256 m's ----
    {
        const float* R  = Rt + b * 9;
        const float* tv = tt + b * 3;
        const float r00 = R[0], r01 = R[1], r02 = R[2];
        const float r10 = R[3], r11 = R[4], r12 = R[5];
        const float r20 = R[6], r21 = R[7], r22 = R[8];
        const float tx = tv[0], ty = tv[1], tz = tv[2];
        const float s2 = s * -2.0f;

        const float* xm = Xt + (size_t)(b * 4096 + mchunk * 256 + tid) * 3;
        const float x = xm[0], y = xm[1], z = xm[2];
        const float ax = r00 * x + r01 * y + r02 * z + tx;
        const float ay = r10 * x + r11 * y + r12 * z + ty;
        const float az = r20 * x + r21 * y + r22 * z + tz;
        const float sq = ax * ax + ay * ay + az * az;
        const int j = tid >> 1, h = tid & 1;
        float* w = (float*)(sm + j * 4);
        w[0 + h] = s2 * ax;   // vx
        w[2 + h] = s2 * ay;   // vy
        w[4 + h] = s2 * az;   // vz
        w[6 + h] = s * sq;    // vw
    }

    // ---- Per-thread: two n's ----
    const float* Rq = Rp + b * 9;
    const float* tq = tp + b * 3;
    const float q00 = Rq[0], q01 = Rq[1], q02 = Rq[2];
    const float q10 = Rq[3], q11 = Rq[4], q12 = Rq[5];
    const float q20 = Rq[6], q21 = Rq[7], q22 = Rq[8];
    const float u0 = tq[0], u1 = tq[1], u2 = tq[2];

    const int n0 = nchunk * 512 + tid;   // and n1 = n0 + 256
    u64 PX[2], PY[2], PZ[2];
    float SC[2];
    #pragma unroll
    for (int i = 0; i < 2; i++) {
        const float* xa = Xp + (size_t)(b * 4096 + n0 + i * 256) * 3;
        const float ax = xa[0], ay = xa[1], az = xa[2];
        const float px = q00 * ax + q01 * ay + q02 * az + u0;
        const float py = q10 * ax + q11 * ay + q12 * az + u1;
        const float pz = q20 * ax + q21 * ay + q22 * az + u2;
        SC[i] = s * (px * px + py * py + pz * pz);
        PX[i] = pk(px, px);
        PY[i] = pk(py, py);
        PZ[i] = pk(pz, pz);
    }

    // Per-chain state. thr = Sh + 60; NS = packed(-Sh). Tile 0 always votes.
    float Sh[2]  = { -1e30f, -1e30f };
    float thr[2] = { -1e30f, -1e30f };
    u64 NS[2] = { pk(1e30f, 1e30f), pk(1e30f, 1e30f) };
    u64 SE[2] = { 0ull, 0ull };
    u64 SG[2] = { 0ull, 0ull };

    __syncthreads();

    // Preload tile 0.
    ulonglong2 va[4], vb[4];
    #pragma unroll
    for (int k = 0; k < 4; k++) {
        va[k] = *(const ulonglong2*)(sm + k * 4);       // vx, vy
        vb[k] = *(const ulonglong2*)(sm + k * 4 + 2);   // vz, vw
    }

    // 32 tiles x (4 groups = 8 m's).
    for (int t = 0; t < 32; t++) {
        // Logits from current registers.
        u64 g[2][4];
        #pragma unroll
        for (int k = 0; k < 4; k++) {
            #pragma unroll
            for (int i = 0; i < 2; i++) {
                u64 a = f2fma(PZ[i], vb[k].x, vb[k].y);
                a = f2fma(PY[i], va[k].y, a);
                g[i][k] = f2fma(PX[i], va[k].x, a);
            }
        }

        // Prefetch next tile (pad makes the last one safe); hidden by exp work.
        {
            const u64* nb = sm + (t + 1) * 16;
            #pragma unroll
            for (int k = 0; k < 4; k++) {
                va[k] = *(const ulonglong2*)(nb + k * 4);
                vb[k] = *(const ulonglong2*)(nb + k * 4 + 2);
            }
        }

        // Tile maxes (ALU pipe) + overflow vote.
        float tm[2];
        bool need = false;
        #pragma unroll
        for (int i = 0; i < 2; i++) {
            float m4[4];
            #pragma unroll
            for (int k = 0; k < 4; k++) { float lo, hi; up(g[i][k], lo, hi); m4[k] = fmaxf(lo, hi); }
            tm[i] = fmaxf(fmaxf(m4[0], m4[1]), fmaxf(m4[2], m4[3]));
            need |= (tm[i] > thr[i]);
        }

        // Rare warp-uniform rescale: raise shift to this tile's max.
        if (__any_sync(0xffffffffu, need)) {
            #pragma unroll
            for (int i = 0; i < 2; i++) {
                const float Shn = fmaxf(Sh[i], tm[i]);
                const float ds = Sh[i] - Shn;        // <= 0, finite
                const float w  = ex2f(ds);
                const u64 D = pk(ds, ds), W = pk(w, w);
                SG[i] = f2mul(f2fma(D, SE[i], SG[i]), W);   // (Sg + ds*Se) * w
                SE[i] = f2mul(SE[i], W);
                Sh[i]  = Shn;
                thr[i] = Shn + 60.0f;
                NS[i]  = pk(-Shn, -Shn);
            }
        }

        // Exp-accumulate against the (lagged) shift. Terms bounded by 2^60.
        #pragma unroll
        for (int i = 0; i < 2; i++) {
            const u64 ns = NS[i];
            u64 se = SE[i], sg = SG[i];
            #pragma unroll
            for (int k = 0; k < 4; k++) {
                const u64 dd = f2add(g[i][k], ns);
                float a0, c0; up(dd, a0, c0);
                const u64 E = pk(ex2f(a0), ex2f(c0));
                se = f2add(se, E);
                sg = f2fma(E, dd, sg);
            }
            SE[i] = se;
            SG[i] = sg;
        }
    }

    // Writeback: partials relative to Sh (no rescale needed; M_c = SC + Sh).
    #pragma unroll
    for (int i = 0; i < 2; i++) {
        float e0, e1, t0, t1;
        up(SE[i], e0, e1);
        up(SG[i], t0, t1);
        const int gi = mchunk * 32768 + b * 4096 + n0 + i * 256;
        g_partE[gi] = e0 + e1;
        g_partT[gi] = t0 + t1;
        g_partM[gi] = SC[i] + Sh[i];
    }
}

// Exact combine: 2 threads per n (8 chunks each), coalesced scalar loads
// (consecutive threads -> consecutive n), halves merged via smem.
// Grid 128 x 512.
__global__ void __launch_bounds__(512) fape_reduce_kernel(
    const float* __restrict__ temp, float* __restrict__ out)
{
    const int j    = threadIdx.x & 255;
    const int half = threadIdx.x >> 8;
    const int n    = blockIdx.x * 256 + j;   // 0..32767
    const int cb   = half * 8;

    float Mc[8];
    float Mh = -CUDART_INF_F;
    #pragma unroll
    for (int i = 0; i < 8; i++) {
        Mc[i] = g_partM[(cb + i) * 32768 + n];
        Mh = fmaxf(Mh, Mc[i]);
    }
    float E = 0.0f, Tg = 0.0f;
    #pragma unroll
    for (int i = 0; i < 8; i++) {
        const float dm = Mc[i] - Mh;                   // <= 0
        const float w  = ex2f(dm);
        const float Ec = g_partE[(cb + i) * 32768 + n];
        const float Tc = g_partT[(cb + i) * 32768 + n];
        E  = fmaf(w, Ec, E);
        Tg = fmaf(w, fmaf(dm, Ec, Tc), Tg);            // w*(Tc + dm*Ec)
    }

    __shared__ float sM[2][256], sE[2][256], sT[2][256];
    sM[half][j] = Mh;
    sE[half][j] = E;
    sT[half][j] = Tg;
    __syncthreads();

    float weighted = 0.0f;
    if (half == 0) {
        const float M0 = sM[0][j], M1 = sM[1][j];
        const float M = fmaxf(M0, M1);
        const float d0 = M0 - M, d1 = M1 - M;
        const float w0 = ex2f(d0), w1 = ex2f(d1);
        const float e0 = sE[0][j], e1 = sE[1][j];
        const float Ef = w0 * e0 + w1 * e1;            // >= 1
        const float Tf = w0 * fmaf(d0, e0, sT[0][j]) + w1 * fmaf(d1, e1, sT[1][j]);
        const float invs = -(*temp) / LOG2E;           // 1/s
        weighted = invs * (Tf / Ef + M) * (1.0f / (8.0f * 4096.0f));
    }

    __shared__ float red[512];
    red[threadIdx.x] = weighted;
    __syncthreads();
    #pragma unroll
    for (int off = 256; off > 0; off >>= 1) {
        if (threadIdx.x < off) red[threadIdx.x] += red[threadIdx.x + off];
        __syncthreads();
    }
    if (threadIdx.x == 0)
        atomicAdd(out, red[0]);
}

extern "C" void kernel_launch(void* const* d_in, const int* in_sizes, int n_in,
                              void* d_out, int out_size) {
    const float* Xp   = (const float*)d_in[0];
    const float* Xt   = (const float*)d_in[1];
    const float* Rp   = (const float*)d_in[2];
    const float* tp   = (const float*)d_in[3];
    const float* Rt   = (const float*)d_in[4];
    const float* tt   = (const float*)d_in[5];
    const float* temp = (const float*)d_in[6];
    float* out = (float*)d_out;

    fape_fused_kernel<<<1024, 256>>>(Xp, Xt, Rp, tp, Rt, tt, temp, out);
    fape_reduce_kernel<<<128, 512>>>(temp, out);
}